// round 1
// baseline (speedup 1.0000x reference)
#include <cuda_runtime.h>

// RevNet additive coupling:
//   x = [x1 | x2] per row (128 + 128 fp32), W is 128x128 fp32
//   y1 = x1
//   y2 = x2 + x1 @ W
//
// Shapes: BATCH*SEQ = 8*32768 = 262144 rows, each row 256 floats in / 256 out.

#define D 128
#define TILE_ROWS 32
#define THREADS 256

static constexpr int ROWS_TOTAL = 8 * 32768;          // 262144
static constexpr int NUM_TILES  = ROWS_TOTAL / TILE_ROWS;  // 8192
static constexpr int SMEM_FLOATS = D * D + TILE_ROWS * D;  // 16384 + 4096
static constexpr int SMEM_BYTES  = SMEM_FLOATS * 4;        // 81920 B

__global__ void __launch_bounds__(THREADS, 2)
revnet_coupling_kernel(const float* __restrict__ x,
                       const float* __restrict__ w,
                       float* __restrict__ out)
{
    extern __shared__ float smem[];
    float* Ws = smem;          // [D][D]          64 KB
    float* Xs = smem + D * D;  // [TILE_ROWS][D]  16 KB

    const int tid = threadIdx.x;

    // Stage W once per block (L2-resident source, 64 KB).
    #pragma unroll 4
    for (int i = tid; i < (D * D) / 4; i += THREADS) {
        ((float4*)Ws)[i] = ((const float4*)w)[i];
    }

    // Thread microtile: 4 rows x 4 cols.
    // cg in [0,32): output cols 4*cg .. 4*cg+3   (warp lanes -> consecutive cols)
    // rg in [0,8):  rows 4*rg .. 4*rg+3          (whole warp shares rg -> x1 LDS broadcast)
    const int cg = tid & 31;
    const int rg = tid >> 5;

    for (int tile = blockIdx.x; tile < NUM_TILES; tile += gridDim.x) {
        __syncthreads();  // protect Xs (and Ws on first iteration)

        const long rowbase = (long)tile * TILE_ROWS;

        // Load x1 tile into SMEM; stream y1 = x1 to output at the same time.
        // 32 rows * 32 float4 = 1024 float4, 4 per thread, fully coalesced.
        #pragma unroll
        for (int i = tid; i < TILE_ROWS * (D / 4); i += THREADS) {
            const int  r = i >> 5;        // D/4 = 32 float4 per row
            const int  c = i & 31;
            const long g = (rowbase + r) * (long)(2 * D) + 4 * c;
            float4 v = *(const float4*)(x + g);
            *(float4*)(Xs + r * D + 4 * c) = v;
            *(float4*)(out + g) = v;      // y1 = x1
        }
        __syncthreads();

        float4 acc[4];
        acc[0] = make_float4(0.f, 0.f, 0.f, 0.f);
        acc[1] = acc[0];
        acc[2] = acc[0];
        acc[3] = acc[0];

        // K loop: per 4 k's, 4 broadcast LDS.128 for x1 rows + 4 conflict-free
        // LDS.128 for W, 64 FFMAs.
        #pragma unroll 2
        for (int k = 0; k < D; k += 4) {
            float4 xv[4];
            #pragma unroll
            for (int i = 0; i < 4; i++)
                xv[i] = *(const float4*)(Xs + (4 * rg + i) * D + k);

            #pragma unroll
            for (int j = 0; j < 4; j++) {
                const float4 wv = *(const float4*)(Ws + (k + j) * D + 4 * cg);
                #pragma unroll
                for (int i = 0; i < 4; i++) {
                    const float xs = (j == 0) ? xv[i].x
                                   : (j == 1) ? xv[i].y
                                   : (j == 2) ? xv[i].z
                                              : xv[i].w;
                    acc[i].x = fmaf(xs, wv.x, acc[i].x);
                    acc[i].y = fmaf(xs, wv.y, acc[i].y);
                    acc[i].z = fmaf(xs, wv.z, acc[i].z);
                    acc[i].w = fmaf(xs, wv.w, acc[i].w);
                }
            }
        }

        // Epilogue: y2 = x2 + acc (coalesced float4 load+store).
        #pragma unroll
        for (int i = 0; i < 4; i++) {
            const long r = rowbase + 4 * rg + i;
            const long g = r * (long)(2 * D) + D + 4 * cg * 1;
            const float4 x2v = *(const float4*)(x + g);
            float4 o;
            o.x = x2v.x + acc[i].x;
            o.y = x2v.y + acc[i].y;
            o.z = x2v.z + acc[i].z;
            o.w = x2v.w + acc[i].w;
            *(float4*)(out + g) = o;
        }
    }
}

extern "C" void kernel_launch(void* const* d_in, const int* in_sizes, int n_in,
                              void* d_out, int out_size)
{
    const float* x = (const float*)d_in[0];   // [8, 32768, 256] fp32
    const float* w = (const float*)d_in[1];   // [128, 128] fp32
    float* out = (float*)d_out;               // [8, 32768, 256] fp32

    cudaFuncSetAttribute(revnet_coupling_kernel,
                         cudaFuncAttributeMaxDynamicSharedMemorySize,
                         SMEM_BYTES);

    // Persistent-ish: 2 blocks per SM (148 SMs), grid-stride over 8192 tiles.
    const int grid = 296;
    revnet_coupling_kernel<<<grid, THREADS, SMEM_BYTES>>>(x, w, out);
}

// round 2
// speedup vs baseline: 1.2231x; 1.2231x over previous
#include <cuda_runtime.h>
#include <cstdint>

// RevNet additive coupling: y1 = x1 ; y2 = x2 + x1 @ W
// x rows: [x1(128) | x2(128)] fp32, W: 128x128 fp32, 262144 rows.
//
// R2: packed fp32 FMA (fma.rn.f32x2) to reach the full 128 FMA/SM/cyc rate,
// 8-row x 4-col thread microtile (64-row block tiles) to cut smem wavefronts.

#define D 128
#define TILE_ROWS 64
#define THREADS 256

static constexpr int ROWS_TOTAL = 8 * 32768;                 // 262144
static constexpr int NUM_TILES  = ROWS_TOTAL / TILE_ROWS;    // 4096
static constexpr int SMEM_FLOATS = D * D + TILE_ROWS * D;    // 16384 + 8192
static constexpr int SMEM_BYTES  = SMEM_FLOATS * 4;          // 98304 B

__device__ __forceinline__ void fma2(uint64_t& d, uint64_t a, uint64_t b) {
    asm("fma.rn.f32x2 %0, %1, %2, %0;" : "+l"(d) : "l"(a), "l"(b));
}
__device__ __forceinline__ uint64_t pack2(float s) {
    uint64_t r;
    asm("mov.b64 %0, {%1, %1};" : "=l"(r) : "f"(s));
    return r;
}

__global__ void __launch_bounds__(THREADS, 2)
revnet_coupling_kernel(const float* __restrict__ x,
                       const float* __restrict__ w,
                       float* __restrict__ out)
{
    extern __shared__ float smem[];
    float* Ws = smem;          // [D][D]           64 KB
    float* Xs = smem + D * D;  // [TILE_ROWS][D]   32 KB

    const int tid = threadIdx.x;

    // Stage W once per block.
    #pragma unroll 4
    for (int i = tid; i < (D * D) / 4; i += THREADS) {
        ((float4*)Ws)[i] = ((const float4*)w)[i];
    }

    // Microtile: warp wi owns rows 8*wi .. 8*wi+7 (x LDS = broadcast),
    // lane owns cols 4*lane .. 4*lane+3 (W LDS.128 conflict-free).
    const int lane = tid & 31;
    const int wi   = tid >> 5;

    for (int tile = blockIdx.x; tile < NUM_TILES; tile += gridDim.x) {
        __syncthreads();  // protect Xs reuse (and Ws on first iter)

        const long rowbase = (long)tile * TILE_ROWS;

        // Load x1 tile -> SMEM; stream y1 = x1 to out (coalesced float4).
        #pragma unroll
        for (int i = tid; i < TILE_ROWS * (D / 4); i += THREADS) {
            const int  r = i >> 5;            // 32 float4 per row
            const int  c = (i & 31) << 2;
            const long g = (rowbase + r) * (long)(2 * D) + c;
            float4 v = *(const float4*)(x + g);
            *(float4*)(Xs + r * D + c) = v;
            *(float4*)(out + g) = v;
        }
        __syncthreads();

        // acc[r][p]: row r (of 8), col-pair p (cols 4*lane+2p, +2p+1)
        uint64_t acc[8][2];
        #pragma unroll
        for (int r = 0; r < 8; r++) { acc[r][0] = 0ull; acc[r][1] = 0ull; }

        const float* xrow = Xs + (wi << 3) * D;
        const float* wcol = Ws + (lane << 2);

        #pragma unroll 2
        for (int k = 0; k < D; k += 4) {
            float4 xv[8];
            #pragma unroll
            for (int r = 0; r < 8; r++)
                xv[r] = *(const float4*)(xrow + r * D + k);

            #pragma unroll
            for (int j = 0; j < 4; j++) {
                const float4 wv = *(const float4*)(wcol + (k + j) * D);
                uint64_t wp0, wp1;
                asm("mov.b64 %0, {%1, %2};" : "=l"(wp0) : "f"(wv.x), "f"(wv.y));
                asm("mov.b64 %0, {%1, %2};" : "=l"(wp1) : "f"(wv.z), "f"(wv.w));
                #pragma unroll
                for (int r = 0; r < 8; r++) {
                    const float xs = (j == 0) ? xv[r].x
                                   : (j == 1) ? xv[r].y
                                   : (j == 2) ? xv[r].z
                                              : xv[r].w;
                    const uint64_t xp = pack2(xs);
                    fma2(acc[r][0], xp, wp0);
                    fma2(acc[r][1], xp, wp1);
                }
            }
        }

        // Epilogue: y2 = x2 + acc, coalesced float4.
        #pragma unroll
        for (int r = 0; r < 8; r++) {
            const long row = rowbase + (wi << 3) + r;
            const long g   = row * (long)(2 * D) + D + (lane << 2);
            const float4 x2v = *(const float4*)(x + g);
            float2 a0 = *(float2*)&acc[r][0];
            float2 a1 = *(float2*)&acc[r][1];
            float4 o;
            o.x = x2v.x + a0.x;
            o.y = x2v.y + a0.y;
            o.z = x2v.z + a1.x;
            o.w = x2v.w + a1.y;
            *(float4*)(out + g) = o;
        }
    }
}

extern "C" void kernel_launch(void* const* d_in, const int* in_sizes, int n_in,
                              void* d_out, int out_size)
{
    const float* x = (const float*)d_in[0];   // [8, 32768, 256] fp32
    const float* w = (const float*)d_in[1];   // [128, 128] fp32
    float* out = (float*)d_out;

    cudaFuncSetAttribute(revnet_coupling_kernel,
                         cudaFuncAttributeMaxDynamicSharedMemorySize,
                         SMEM_BYTES);

    const int grid = 296;  // 2 blocks/SM x 148 SMs
    revnet_coupling_kernel<<<grid, THREADS, SMEM_BYTES>>>(x, w, out);
}

// round 3
// speedup vs baseline: 1.2890x; 1.0538x over previous
#include <cuda_runtime.h>
#include <cstdint>

// RevNet additive coupling: y1 = x1 ; y2 = x2 + x1 @ W
// x rows: [x1(128) | x2(128)] fp32, W: 128x128 fp32, 262144 rows.
//
// R3: cp.async double-buffered pipeline (x1 AND x2 tiles prefetched to smem)
// to overlap DRAM with the packed-FMA mainloop. 1 block/SM, 192 KB smem.

#define D 128
#define TILE_ROWS 64
#define THREADS 256

static constexpr int ROWS_TOTAL = 8 * 32768;               // 262144
static constexpr int NUM_TILES  = ROWS_TOTAL / TILE_ROWS;  // 4096
static constexpr int TILE_F     = TILE_ROWS * D;           // 8192 floats
// W(16384) + 2*X1(8192) + 2*X2(8192) = 49152 floats = 192 KB
static constexpr int SMEM_BYTES = (D * D + 4 * TILE_F) * 4;

__device__ __forceinline__ void fma2(uint64_t& d, uint64_t a, uint64_t b) {
    asm("fma.rn.f32x2 %0, %1, %2, %0;" : "+l"(d) : "l"(a), "l"(b));
}
__device__ __forceinline__ uint64_t pack2(float s) {
    uint64_t r;
    asm("mov.b64 %0, {%1, %1};" : "=l"(r) : "f"(s));
    return r;
}
__device__ __forceinline__ void cp16(float* smem_dst, const float* gsrc) {
    uint32_t s = (uint32_t)__cvta_generic_to_shared(smem_dst);
    asm volatile("cp.async.cg.shared.global [%0], [%1], 16;" :: "r"(s), "l"(gsrc));
}

__global__ void __launch_bounds__(THREADS, 1)
revnet_coupling_kernel(const float* __restrict__ x,
                       const float* __restrict__ w,
                       float* __restrict__ out)
{
    extern __shared__ float smem[];
    float* Ws  = smem;                 // [128][128]       64 KB
    float* X1s = smem + D * D;         // [2][64][128]     64 KB
    float* X2s = X1s + 2 * TILE_F;     // [2][64][128]     64 KB

    const int tid  = threadIdx.x;
    const int lane = tid & 31;
    const int wi   = tid >> 5;

    // Stage W once (visibility covered by the first __syncthreads below).
    #pragma unroll 4
    for (int i = tid; i < (D * D) / 4; i += THREADS)
        ((float4*)Ws)[i] = ((const float4*)w)[i];

    // Async-load one tile (x1 + x2 halves) into buffer b.
    auto issue_tile = [&](int t, int b) {
        const long rowbase = (long)t * TILE_ROWS;
        float* x1d = X1s + b * TILE_F;
        float* x2d = X2s + b * TILE_F;
        #pragma unroll
        for (int i = tid; i < TILE_ROWS * (D / 4); i += THREADS) {
            const int  r = i >> 5;            // 32 float4 per row
            const int  c = (i & 31) << 2;
            const float* g = x + (rowbase + r) * (long)(2 * D) + c;
            cp16(x1d + r * D + c, g);         // x1
            cp16(x2d + r * D + c, g + D);     // x2
        }
        asm volatile("cp.async.commit_group;");
    };

    int tile = blockIdx.x;
    if (tile < NUM_TILES) issue_tile(tile, 0);

    int buf = 0;
    for (; tile < NUM_TILES; tile += gridDim.x, buf ^= 1) {
        const int  nxt      = tile + gridDim.x;
        const bool has_next = nxt < NUM_TILES;

        if (has_next) {
            issue_tile(nxt, buf ^ 1);
            asm volatile("cp.async.wait_group 1;");
        } else {
            asm volatile("cp.async.wait_group 0;");
        }
        __syncthreads();   // current buffer (and W on iter 0) visible to all

        const long   rowbase = (long)tile * TILE_ROWS;
        const float* x1b = X1s + buf * TILE_F;
        const float* x2b = X2s + buf * TILE_F;

        // y1 = x1: stream out from smem (coalesced float4 stores).
        #pragma unroll
        for (int i = tid; i < TILE_ROWS * (D / 4); i += THREADS) {
            const int  r = i >> 5;
            const int  c = (i & 31) << 2;
            const long g = (rowbase + r) * (long)(2 * D) + c;
            *(float4*)(out + g) = *(const float4*)(x1b + r * D + c);
        }

        // Mainloop: warp wi owns rows 8*wi..8*wi+7 (broadcast LDS),
        // lane owns cols 4*lane..4*lane+3 (conflict-free LDS.128 on W).
        uint64_t acc[8][2];
        #pragma unroll
        for (int r = 0; r < 8; r++) { acc[r][0] = 0ull; acc[r][1] = 0ull; }

        const float* xrow = x1b + (wi << 3) * D;
        const float* wcol = Ws + (lane << 2);

        #pragma unroll 2
        for (int k = 0; k < D; k += 4) {
            float4 xv[8];
            #pragma unroll
            for (int r = 0; r < 8; r++)
                xv[r] = *(const float4*)(xrow + r * D + k);

            #pragma unroll
            for (int j = 0; j < 4; j++) {
                const float4 wv = *(const float4*)(wcol + (k + j) * D);
                uint64_t wp0, wp1;
                asm("mov.b64 %0, {%1, %2};" : "=l"(wp0) : "f"(wv.x), "f"(wv.y));
                asm("mov.b64 %0, {%1, %2};" : "=l"(wp1) : "f"(wv.z), "f"(wv.w));
                #pragma unroll
                for (int r = 0; r < 8; r++) {
                    const float xs = (j == 0) ? xv[r].x
                                   : (j == 1) ? xv[r].y
                                   : (j == 2) ? xv[r].z
                                              : xv[r].w;
                    const uint64_t xp = pack2(xs);
                    fma2(acc[r][0], xp, wp0);
                    fma2(acc[r][1], xp, wp1);
                }
            }
        }

        // Epilogue: y2 = x2 + acc (x2 from smem, conflict-free LDS.128).
        #pragma unroll
        for (int r = 0; r < 8; r++) {
            const int  rl = (wi << 3) + r;
            const long g  = (rowbase + rl) * (long)(2 * D) + D + (lane << 2);
            const float4 x2v = *(const float4*)(x2b + rl * D + (lane << 2));
            float2 a0 = *(float2*)&acc[r][0];
            float2 a1 = *(float2*)&acc[r][1];
            float4 o;
            o.x = x2v.x + a0.x;
            o.y = x2v.y + a0.y;
            o.z = x2v.z + a1.x;
            o.w = x2v.w + a1.y;
            *(float4*)(out + g) = o;
        }

        __syncthreads();   // all reads of `buf` done before it is refilled
    }
}

extern "C" void kernel_launch(void* const* d_in, const int* in_sizes, int n_in,
                              void* d_out, int out_size)
{
    const float* x = (const float*)d_in[0];   // [8, 32768, 256] fp32
    const float* w = (const float*)d_in[1];   // [128, 128] fp32
    float* out = (float*)d_out;

    cudaFuncSetAttribute(revnet_coupling_kernel,
                         cudaFuncAttributeMaxDynamicSharedMemorySize,
                         SMEM_BYTES);

    const int grid = 148;  // persistent, 1 block/SM
    revnet_coupling_kernel<<<grid, THREADS, SMEM_BYTES>>>(x, w, out);
}